// round 14
// baseline (speedup 1.0000x reference)
#include <cuda_runtime.h>
#include <cuda_fp16.h>
#include <cstdint>

#define NTH 384

namespace {
constexpr int E    = 32;
constexpr int TOK  = 112;             // 7 m-tiles of 16
constexpr int NCTA = (16384 + TOK - 1) / TOK;   // 147
constexpr int BTOT = 16384;

constexpr int EXP_B32   = 40960;
constexpr int TOTAL_B32 = E * EXP_B32 + 2048;  // + B5 gate-GEMM block
constexpr int TOTAL_F16 = TOTAL_B32 * 2;

// per-expert byte bases inside g_Wh (fragment-linear, full-N blocks)
constexpr int BYT_S1 = 0;        // K=256,N=64
constexpr int BYT_S2 = 32768;    // K=64, N=256
constexpr int BYT_S3 = 65536;    // K=256,N=128
constexpr int BYT_S4 = 131072;   // K=128,N=64
constexpr int BYT_S5 = 147456;   // K=64, N=128
constexpr int EXP_BYTES = 163840;
constexpr int BYT_B5 = E * EXP_BYTES;   // K=32, N=128

// smem byte offsets (7 m-tiles)
constexpr int OFF_SX   = 0;        // x A-frag (K16=16): 57344
constexpr int OFF_H2   = 57344;    // h2 A-frag (K16=16): 57344 (also Wg staging)
constexpr int OFF_H3   = 114688;   // h3 A-frag (K16=8): 28672 (also logits tmp)
constexpr int OFF_H64A = 143360;   // h1 A-frag: 14336
constexpr int OFF_H64B = 157696;   // h4 A-frag: 14336
constexpr int OFF_G    = 172032;   // gates f32 [E][112]: 14336
constexpr int OFF_GF   = 186368;   // gate A-frag f16 (K16=2): 7168
constexpr int SMEM_BYTES = 193536; // 1 CTA/SM

__device__ __align__(16) __half g_Wh[TOTAL_F16];
}

// ---------------- helpers ----------------
__device__ __forceinline__ uint32_t smem_u32(const void* p) {
    uint32_t a;
    asm("{ .reg .u64 t; cvta.to.shared.u64 t, %1; cvt.u32.u64 %0, t; }" : "=r"(a) : "l"(p));
    return a;
}
__device__ __forceinline__ uint32_t packh(float lo, float hi) {
    uint32_t r;
    asm("cvt.rn.f16x2.f32 %0, %1, %2;" : "=r"(r) : "f"(hi), "f"(lo));
    return r;
}
__device__ __forceinline__ void mma16(float* d, const uint32_t* a, uint32_t b0, uint32_t b1) {
    asm volatile("mma.sync.aligned.m16n8k16.row.col.f32.f16.f16.f32 "
        "{%0,%1,%2,%3}, {%4,%5,%6,%7}, {%8,%9}, {%0,%1,%2,%3};"
        : "+f"(d[0]), "+f"(d[1]), "+f"(d[2]), "+f"(d[3])
        : "r"(a[0]), "r"(a[1]), "r"(a[2]), "r"(a[3]), "r"(b0), "r"(b1));
}
__device__ __forceinline__ void lds128(uint32_t* r, uint32_t addr) {
    asm volatile("ld.shared.v4.u32 {%0,%1,%2,%3}, [%4];"
        : "=r"(r[0]), "=r"(r[1]), "=r"(r[2]), "=r"(r[3]) : "r"(addr));
}
__device__ __forceinline__ void sts64(uint32_t addr, uint32_t h0, uint32_t h1) {
    asm volatile("st.shared.v2.u32 [%0], {%1,%2};" :: "r"(addr), "r"(h0), "r"(h1) : "memory");
}
__device__ __forceinline__ void ldg128(uint32_t* r, const char* p) {
    uint4 v = __ldg(reinterpret_cast<const uint4*>(p));
    r[0] = v.x; r[1] = v.y; r[2] = v.z; r[3] = v.w;
}

// ---------------- weight repack (gather form: coalesced 16B writes) ----------------
__global__ void repack_all(const float* __restrict__ W1, const float* __restrict__ W2,
                           const float* __restrict__ W3, const float* __restrict__ W4,
                           const float* __restrict__ W5, const float* __restrict__ b5) {
    int t = blockIdx.x * blockDim.x + threadIdx.x;
    int w0 = t * 4;
    if (w0 >= TOTAL_B32) return;

    const float* W; int K, NSRC, roff; size_t erow = 0;
    if (w0 < E * EXP_B32) {
        int e = w0 / EXP_B32, r = w0 % EXP_B32;
        if      (r <  8192) { W = W1; K = 256; NSRC =  64; roff = r; }
        else if (r < 16384) { W = W2; K =  64; NSRC = 256; roff = r - 8192; }
        else if (r < 32768) { W = W3; K = 256; NSRC = 128; roff = r - 16384; }
        else if (r < 36864) { W = W4; K = 128; NSRC =  64; roff = r - 32768; }
        else                { W = W5; K =  64; NSRC = 128; roff = r - 36864; }
        erow = (size_t)e * K * NSRC;
    } else {
        W = b5; K = 32; NSRC = 128; roff = w0 - E * EXP_B32;
    }

    int block = roff >> 7, inner = roff & 127;
    int nt16 = block % (NSRC >> 4), kt16 = block / (NSRC >> 4);
    int kq = (inner >> 2) & 3, nl = (inner >> 4) & 7;
    int kb = kt16 * 16 + kq * 2, nb = nt16 * 16 + nl;
    const float* src = W + erow;

    uint32_t wv[4];
    #pragma unroll
    for (int i = 0; i < 4; ++i) {
        int k = kb + (i & 1) * 8;
        int n = nb + ((i >> 1) & 1) * 8;
        float lo = src[(size_t)k * NSRC + n];
        float hi = src[(size_t)(k + 1) * NSRC + n];
        wv[i] = packh(lo, hi);
    }
    uint4 o; o.x = wv[0]; o.y = wv[1]; o.z = wv[2]; o.w = wv[3];
    *reinterpret_cast<uint4*>(reinterpret_cast<char*>(g_Wh) + (size_t)w0 * 4) = o;
}

// ---------------- fused stage (MT m-tiles starting at MTB, NT n-tiles per warp) ----------------
// MODE 0: relu -> A-frag STS ; MODE 1: relu*gate -> STS ; MODE 2: accumulate into dacc.
template<int MT, int MTB, int K16TOT, int NT, int KSTR, int K16OUT, int MODE, int RING, bool ALOOK>
__device__ __forceinline__ void stage(
    uint32_t smA, uint32_t smOut, uint32_t koff_out,
    const char* __restrict__ gB,
    const float* __restrict__ bias,
    const float* __restrict__ gate,
    float* __restrict__ dacc,
    int tid)
{
    const int lane = tid & 31;
    const int wn = (tid >> 5) & 3;
    const int c = lane & 3, ri = lane >> 2;
    constexpr int NFR = NT / 2;

    float dtmp[MODE == 2 ? 1 : MT * NT * 4];
    float* d = (MODE == 2) ? dacc : dtmp;
    if (MODE != 2) {
        #pragma unroll
        for (int j = 0; j < MT * NT * 4; ++j) d[j] = 0.f;
    }

    const char* gw = gB + (size_t)((wn * NFR * 32 + lane) * 16);

    uint32_t bq[RING][NFR][4];
    #pragma unroll
    for (int i = 0; i < RING - 1 && i < K16TOT; ++i)
        #pragma unroll
        for (int p = 0; p < NFR; ++p)
            ldg128(bq[i][p], gw + (size_t)((i * KSTR + p) * 512));

    uint32_t a[ALOOK ? 2 : 1][MT][4];
    if (ALOOK) {
        #pragma unroll
        for (int mt = 0; mt < MT; ++mt)
            lds128(a[0][mt], smA + (uint32_t)((((MTB + mt) * K16TOT) * 32 + lane) * 16));
    }

    #pragma unroll
    for (int k16 = 0; k16 < K16TOT; ++k16) {
        if (k16 + (RING - 1) < K16TOT) {
            #pragma unroll
            for (int p = 0; p < NFR; ++p)
                ldg128(bq[(k16 + RING - 1) % RING][p],
                       gw + (size_t)(((k16 + RING - 1) * KSTR + p) * 512));
        }
        if (ALOOK) {
            if (k16 + 1 < K16TOT) {
                #pragma unroll
                for (int mt = 0; mt < MT; ++mt)
                    lds128(a[(k16 + 1) & 1][mt],
                           smA + (uint32_t)((((MTB + mt) * K16TOT + k16 + 1) * 32 + lane) * 16));
            }
        } else {
            #pragma unroll
            for (int mt = 0; mt < MT; ++mt)
                lds128(a[0][mt],
                       smA + (uint32_t)((((MTB + mt) * K16TOT + k16) * 32 + lane) * 16));
        }
        const uint32_t (*ac)[4] = ALOOK ? a[k16 & 1] : a[0];
        #pragma unroll
        for (int p = 0; p < NFR; ++p) {
            const uint32_t* b = bq[k16 % RING][p];
            #pragma unroll
            for (int mt = 0; mt < MT; ++mt) {
                mma16(d + (mt * NT + 2 * p) * 4,     ac[mt], b[0], b[1]);
                mma16(d + (mt * NT + 2 * p + 1) * 4, ac[mt], b[2], b[3]);
            }
        }
    }

    if (MODE == 2) return;

    #pragma unroll
    for (int mt = 0; mt < MT; ++mt) {
        const int r0 = (MTB + mt) * 16 + ri;
        float g0 = 1.f, g1 = 1.f;
        if (MODE == 1) { g0 = gate[r0]; g1 = gate[r0 + 8]; }
        #pragma unroll
        for (int t8 = 0; t8 < NT; ++t8) {
            const int n0 = wn * (NT * 8) + t8 * 8 + 2 * c;
            const float bz0 = __ldg(bias + n0), bz1 = __ldg(bias + n0 + 1);
            const float* dd = d + (mt * NT + t8) * 4;
            float v0 = fmaxf(dd[0] + bz0, 0.f), v1 = fmaxf(dd[1] + bz1, 0.f);
            float v2 = fmaxf(dd[2] + bz0, 0.f), v3 = fmaxf(dd[3] + bz1, 0.f);
            if (MODE == 1) { v0 *= g0; v1 *= g0; v2 *= g1; v3 *= g1; }
            uint32_t h0 = packh(v0, v1), h1 = packh(v2, v3);
            uint32_t dst = smOut
                + (uint32_t)((((MTB + mt) * K16OUT + koff_out + ((wn * NT + t8) >> 1)) * 32
                              + lane) * 16)
                + (uint32_t)((t8 & 1) * 8);
            sts64(dst, h0, h1);
        }
    }
}

// dispatch three wm variants (warp-uniform branch); barriers OUTSIDE
#define STAGE(K16TOT, NT, KSTR, K16OUT, MODE, RING, ALOOK, smA, smOut, koff, gB, bias, gate, dacc) \
    do { if (wmg == 0)      stage<3, 0, K16TOT, NT, KSTR, K16OUT, MODE, RING, ALOOK>(              \
                               smA, smOut, koff, gB, bias, gate, dacc, tid);                       \
         else if (wmg == 1) stage<2, 3, K16TOT, NT, KSTR, K16OUT, MODE, RING, ALOOK>(              \
                               smA, smOut, koff, gB, bias, gate, dacc, tid);                       \
         else               stage<2, 5, K16TOT, NT, KSTR, K16OUT, MODE, RING, ALOOK>(              \
                               smA, smOut, koff, gB, bias, gate, dacc, tid); } while (0)

// ---------------- main kernel ----------------
__global__ void __launch_bounds__(NTH, 1) moe_f16_kernel(
    const float* __restrict__ x,
    const float* __restrict__ Wg, const float* __restrict__ bg,
    const float* __restrict__ b1, const float* __restrict__ b2,
    const float* __restrict__ b3, const float* __restrict__ b4,
    float* __restrict__ out)
{
    extern __shared__ char smem[];
    const uint32_t smb = smem_u32(smem);
    const uint32_t smX = smb + OFF_SX, smH2 = smb + OFF_H2;
    const uint32_t smH3 = smb + OFF_H3;
    const uint32_t smH64A = smb + OFF_H64A, smH64B = smb + OFF_H64B;
    const uint32_t smGF = smb + OFF_GF;
    float* sWg  = reinterpret_cast<float*>(smem + OFF_H2);
    float* sLog = reinterpret_cast<float*>(smem + OFF_H3);
    float* sG   = reinterpret_cast<float*>(smem + OFF_G);

    const int tid = threadIdx.x;
    const int b0  = blockIdx.x * TOK;

    // ---- x -> A-fragment f16 layout (112 tok, K16=16); OOB tokens -> 0 ----
    for (int i = 0; i < 38; ++i) {
        int u = tid + i * NTH;            // b32 unit over 112 tok x 128 k-pairs
        if (u >= 112 * 128) break;
        int tok = u >> 7, k2 = u & 127;
        int k = 2 * k2;
        float2 v = make_float2(0.f, 0.f);
        if (b0 + tok < BTOT)
            v = *reinterpret_cast<const float2*>(x + (size_t)(b0 + tok) * 256 + k);
        uint32_t h = packh(v.x, v.y);
        uint32_t b32i = (uint32_t)(((tok >> 4) * 16 + (k >> 4)) * 128
                      + ((tok & 7) * 4 + ((k >> 1) & 3)) * 4
                      + ((k >> 3) & 1) * 2 + ((tok >> 3) & 1));
        *reinterpret_cast<uint32_t*>(smem + OFF_SX + b32i * 4) = h;
    }
    // Wg -> smem staging (32KB in H2 area)
    {
        const float4* s4 = reinterpret_cast<const float4*>(Wg);
        float4* d4 = reinterpret_cast<float4*>(smem + OFF_H2);
        #pragma unroll
        for (int i = 0; i < 6; ++i) {
            int u = tid + i * NTH;
            if (u < 2048) d4[u] = s4[u];
        }
    }
    __syncthreads();

    // ---- gating logits (fp32, x from gmem, guarded) ----
    if (tid < 224) {
        int tok = tid >> 1, eg = (tid & 1) * 16;
        float lg[16];
        #pragma unroll
        for (int j = 0; j < 16; ++j) lg[j] = 0.f;
        const bool ok = (b0 + tok < BTOT);
        const float* xr = x + (size_t)(b0 + tok) * 256;
        #pragma unroll 2
        for (int k = 0; k < 256; ++k) {
            float a = ok ? __ldg(xr + k) : 0.f;
            const float* wr = sWg + k * 32 + eg;
            #pragma unroll
            for (int q = 0; q < 4; ++q) {
                float4 w = *reinterpret_cast<const float4*>(wr + 4 * q);
                lg[4*q+0] += a * w.x; lg[4*q+1] += a * w.y;
                lg[4*q+2] += a * w.z; lg[4*q+3] += a * w.w;
            }
        }
        #pragma unroll
        for (int j = 0; j < 16; ++j) sLog[tok * 32 + eg + j] = lg[j] + __ldg(bg + eg + j);
    }
    __syncthreads();
    // softmax; store f32 gates [e][tok] and f16 gate A-fragments (K=32 -> 2 k16)
    if (tid < TOK) {
        float lv[32];
        float m = -1e30f;
        #pragma unroll
        for (int e2 = 0; e2 < 32; ++e2) { lv[e2] = sLog[tid * 32 + e2]; m = fmaxf(m, lv[e2]); }
        float s = 0.f;
        #pragma unroll
        for (int e2 = 0; e2 < 32; ++e2) { lv[e2] = expf(lv[e2] - m); s += lv[e2]; }
        float inv = 1.f / s;
        #pragma unroll
        for (int e2 = 0; e2 < 32; ++e2) lv[e2] *= inv;
        #pragma unroll
        for (int e2 = 0; e2 < 32; ++e2) sG[e2 * TOK + tid] = lv[e2];
        #pragma unroll
        for (int e2 = 0; e2 < 32; e2 += 2) {
            uint32_t h = packh(lv[e2], lv[e2 + 1]);
            uint32_t b32i = (uint32_t)(((tid >> 4) * 2 + (e2 >> 4)) * 128
                          + ((tid & 7) * 4 + ((e2 >> 1) & 3)) * 4
                          + ((e2 >> 3) & 1) * 2 + ((tid >> 3) & 1));
            *reinterpret_cast<uint32_t*>(smem + OFF_GF + b32i * 4) = h;
        }
    }
    __syncthreads();

    // ---- expert loop; persistent output accumulator (MT<=3 -> 48 floats) ----
    float dacc[48];
    #pragma unroll
    for (int j = 0; j < 48; ++j) dacc[j] = 0.f;

    const char* gWh = reinterpret_cast<const char*>(g_Wh);
    const int wmg = (tid >> 5) >> 2;   // 0,1,2

    for (int e = 0; e < E; ++e) {
        const char* wb = gWh + (size_t)e * EXP_BYTES;
        // S1: K=256, N=64 -> H64A (ring4, A-lookahead)
        STAGE(16, 2, 4, 4, 0, 4, true, smX, smH64A, 0, wb + BYT_S1,
              b1 + e * 64, nullptr, nullptr);
        __syncthreads();
        // S2: K=64, N=256 as two N=128 halves -> H2
        STAGE(4, 4, 16, 16, 0, 3, false, smH64A, smH2, 0, wb + BYT_S2,
              b2 + e * 256, nullptr, nullptr);
        STAGE(4, 4, 16, 16, 0, 3, false, smH64A, smH2, 8, wb + BYT_S2 + 4096,
              b2 + e * 256 + 128, nullptr, nullptr);
        __syncthreads();
        // S3: K=256, N=128 -> H3
        STAGE(16, 4, 8, 8, 0, 3, false, smH2, smH3, 0, wb + BYT_S3,
              b3 + e * 128, nullptr, nullptr);
        __syncthreads();
        // S4: K=128, N=64 -> H64B, relu*gate folded (ring4, A-lookahead)
        STAGE(8, 2, 4, 4, 1, 4, true, smH3, smH64B, 0, wb + BYT_S4,
              b4 + e * 64, sG + e * TOK, nullptr);
        __syncthreads();
        // S5: K=64, N=128, accumulate into dacc (no trailing sync: H64A/B split)
        STAGE(4, 4, 8, 0, 2, 3, false, smH64B, 0, 0, wb + BYT_S5,
              nullptr, nullptr, dacc);
    }

    // ---- bias term: dacc += G[112,32] @ B5[32,128] ----
    STAGE(2, 4, 8, 0, 2, 2, false, smGF, 0, 0, gWh + (size_t)BYT_B5,
          nullptr, nullptr, dacc);

    // ---- write output, guarded ----
    {
        const int lane = tid & 31, wid = tid >> 5;
        const int wn = wid & 3;
        const int ri = lane >> 2, c = lane & 3;
        const int MT = (wmg == 0) ? 3 : 2;
        const int MTB = (wmg == 0) ? 0 : (wmg == 1 ? 3 : 5);
        for (int mt = 0; mt < MT; ++mt) {
            int r0 = b0 + (MTB + mt) * 16 + ri;
            #pragma unroll
            for (int t8 = 0; t8 < 4; ++t8) {
                int n0 = wn * 32 + t8 * 8 + 2 * c;
                const float* o = dacc + (mt * 4 + t8) * 4;
                float2 v0; v0.x = o[0]; v0.y = o[1];
                float2 v1; v1.x = o[2]; v1.y = o[3];
                if (r0 < BTOT)
                    *reinterpret_cast<float2*>(out + (size_t)r0 * 128 + n0) = v0;
                if (r0 + 8 < BTOT)
                    *reinterpret_cast<float2*>(out + (size_t)(r0 + 8) * 128 + n0) = v1;
            }
        }
    }
}

// ---------------- launcher ----------------
extern "C" void kernel_launch(void* const* d_in, const int* in_sizes, int n_in,
                              void* d_out, int out_size)
{
    (void)in_sizes; (void)n_in; (void)out_size;
    const float* x  = (const float*)d_in[0];
    const float* Wg = (const float*)d_in[1];
    const float* bg = (const float*)d_in[2];
    const float* W1 = (const float*)d_in[3];
    const float* b1 = (const float*)d_in[4];
    const float* W2 = (const float*)d_in[5];
    const float* b2 = (const float*)d_in[6];
    const float* W3 = (const float*)d_in[7];
    const float* b3 = (const float*)d_in[8];
    const float* W4 = (const float*)d_in[9];
    const float* b4 = (const float*)d_in[10];
    const float* W5 = (const float*)d_in[11];
    const float* b5 = (const float*)d_in[12];
    float* out = (float*)d_out;

    repack_all<<<(TOTAL_B32 / 4 + 255) / 256, 256>>>(W1, W2, W3, W4, W5, b5);

    cudaFuncSetAttribute(moe_f16_kernel,
                         cudaFuncAttributeMaxDynamicSharedMemorySize, SMEM_BYTES);
    moe_f16_kernel<<<NCTA, NTH, SMEM_BYTES>>>(x, Wg, bg, b1, b2, b3, b4, out);
}

// round 15
// speedup vs baseline: 1.0616x; 1.0616x over previous
#include <cuda_runtime.h>
#include <cuda_fp16.h>
#include <cstdint>

#define NTH 256

namespace {
constexpr int E    = 32;
constexpr int TOK  = 112;             // 7 m-tiles of 16
constexpr int NCTA = (16384 + TOK - 1) / TOK;   // 147
constexpr int BTOT = 16384;

constexpr int EXP_B32   = 40960;
constexpr int TOTAL_B32 = E * EXP_B32 + 2048;  // + B5 gate-GEMM block
constexpr int TOTAL_F16 = TOTAL_B32 * 2;

// per-expert byte bases inside g_Wh (fragment-linear, full-N blocks)
constexpr int BYT_S1 = 0;        // K=256,N=64
constexpr int BYT_S2 = 32768;    // K=64, N=256
constexpr int BYT_S3 = 65536;    // K=256,N=128
constexpr int BYT_S4 = 131072;   // K=128,N=64
constexpr int BYT_S5 = 147456;   // K=64, N=128
constexpr int EXP_BYTES = 163840;
constexpr int BYT_B5 = E * EXP_BYTES;   // K=32, N=128

// smem byte offsets (7 m-tiles)
constexpr int OFF_SX   = 0;        // x A-frag (K16=16): 57344
constexpr int OFF_H2   = 57344;    // h2 A-frag (K16=16): 57344 (also Wg staging)
constexpr int OFF_H3   = 114688;   // h3 A-frag (K16=8): 28672 (also logits tmp)
constexpr int OFF_H64A = 143360;   // h1 A-frag: 14336
constexpr int OFF_H64B = 157696;   // h4 A-frag: 14336
constexpr int OFF_G    = 172032;   // gates f32 [E][112]: 14336
constexpr int OFF_GF   = 186368;   // gate A-frag f16 (K16=2): 7168
constexpr int SMEM_BYTES = 193536; // 1 CTA/SM

__device__ __align__(16) __half g_Wh[TOTAL_F16];
}

// ---------------- helpers ----------------
__device__ __forceinline__ uint32_t smem_u32(const void* p) {
    uint32_t a;
    asm("{ .reg .u64 t; cvta.to.shared.u64 t, %1; cvt.u32.u64 %0, t; }" : "=r"(a) : "l"(p));
    return a;
}
__device__ __forceinline__ uint32_t packh(float lo, float hi) {
    uint32_t r;
    asm("cvt.rn.f16x2.f32 %0, %1, %2;" : "=r"(r) : "f"(hi), "f"(lo));
    return r;
}
__device__ __forceinline__ void mma16(float* d, const uint32_t* a, uint32_t b0, uint32_t b1) {
    asm volatile("mma.sync.aligned.m16n8k16.row.col.f32.f16.f16.f32 "
        "{%0,%1,%2,%3}, {%4,%5,%6,%7}, {%8,%9}, {%0,%1,%2,%3};"
        : "+f"(d[0]), "+f"(d[1]), "+f"(d[2]), "+f"(d[3])
        : "r"(a[0]), "r"(a[1]), "r"(a[2]), "r"(a[3]), "r"(b0), "r"(b1));
}
__device__ __forceinline__ void lds128(uint32_t* r, uint32_t addr) {
    asm volatile("ld.shared.v4.u32 {%0,%1,%2,%3}, [%4];"
        : "=r"(r[0]), "=r"(r[1]), "=r"(r[2]), "=r"(r[3]) : "r"(addr));
}
__device__ __forceinline__ void sts64(uint32_t addr, uint32_t h0, uint32_t h1) {
    asm volatile("st.shared.v2.u32 [%0], {%1,%2};" :: "r"(addr), "r"(h0), "r"(h1) : "memory");
}
__device__ __forceinline__ void ldg128(uint32_t* r, const char* p) {
    uint4 v = __ldg(reinterpret_cast<const uint4*>(p));
    r[0] = v.x; r[1] = v.y; r[2] = v.z; r[3] = v.w;
}

// ---------------- weight repack (gather form: coalesced 16B writes) ----------------
__global__ void repack_all(const float* __restrict__ W1, const float* __restrict__ W2,
                           const float* __restrict__ W3, const float* __restrict__ W4,
                           const float* __restrict__ W5, const float* __restrict__ b5) {
    int t = blockIdx.x * blockDim.x + threadIdx.x;
    int w0 = t * 4;
    if (w0 >= TOTAL_B32) return;

    const float* W; int K, NSRC, roff; size_t erow = 0;
    if (w0 < E * EXP_B32) {
        int e = w0 / EXP_B32, r = w0 % EXP_B32;
        if      (r <  8192) { W = W1; K = 256; NSRC =  64; roff = r; }
        else if (r < 16384) { W = W2; K =  64; NSRC = 256; roff = r - 8192; }
        else if (r < 32768) { W = W3; K = 256; NSRC = 128; roff = r - 16384; }
        else if (r < 36864) { W = W4; K = 128; NSRC =  64; roff = r - 32768; }
        else                { W = W5; K =  64; NSRC = 128; roff = r - 36864; }
        erow = (size_t)e * K * NSRC;
    } else {
        W = b5; K = 32; NSRC = 128; roff = w0 - E * EXP_B32;
    }

    int block = roff >> 7, inner = roff & 127;
    int nt16 = block % (NSRC >> 4), kt16 = block / (NSRC >> 4);
    int kq = (inner >> 2) & 3, nl = (inner >> 4) & 7;
    int kb = kt16 * 16 + kq * 2, nb = nt16 * 16 + nl;
    const float* src = W + erow;

    uint32_t wv[4];
    #pragma unroll
    for (int i = 0; i < 4; ++i) {
        int k = kb + (i & 1) * 8;
        int n = nb + ((i >> 1) & 1) * 8;
        float lo = src[(size_t)k * NSRC + n];
        float hi = src[(size_t)(k + 1) * NSRC + n];
        wv[i] = packh(lo, hi);
    }
    uint4 o; o.x = wv[0]; o.y = wv[1]; o.z = wv[2]; o.w = wv[3];
    *reinterpret_cast<uint4*>(reinterpret_cast<char*>(g_Wh) + (size_t)w0 * 4) = o;
}

// ---------------- fused stage (MT m-tiles starting at MTB, NT n-tiles per warp) ----------------
// MODE 0: relu -> A-frag STS ; MODE 1: relu*gate -> STS ; MODE 2: accumulate into dacc.
template<int MT, int MTB, int K16TOT, int NT, int KSTR, int K16OUT, int MODE, int RING, bool ALOOK>
__device__ __forceinline__ void stage(
    uint32_t smA, uint32_t smOut, uint32_t koff_out,
    const char* __restrict__ gB,
    const float* __restrict__ bias,
    const float* __restrict__ gate,
    float* __restrict__ dacc,
    int tid)
{
    const int lane = tid & 31;
    const int wn = (tid >> 5) & 3;
    const int c = lane & 3, ri = lane >> 2;
    constexpr int NFR = NT / 2;

    float dtmp[MODE == 2 ? 1 : MT * NT * 4];
    float* d = (MODE == 2) ? dacc : dtmp;
    if (MODE != 2) {
        #pragma unroll
        for (int j = 0; j < MT * NT * 4; ++j) d[j] = 0.f;
    }

    const char* gw = gB + (size_t)((wn * NFR * 32 + lane) * 16);

    uint32_t bq[RING][NFR][4];
    #pragma unroll
    for (int i = 0; i < RING - 1 && i < K16TOT; ++i)
        #pragma unroll
        for (int p = 0; p < NFR; ++p)
            ldg128(bq[i][p], gw + (size_t)((i * KSTR + p) * 512));

    uint32_t a[ALOOK ? 2 : 1][MT][4];
    if (ALOOK) {
        #pragma unroll
        for (int mt = 0; mt < MT; ++mt)
            lds128(a[0][mt], smA + (uint32_t)((((MTB + mt) * K16TOT) * 32 + lane) * 16));
    }

    #pragma unroll
    for (int k16 = 0; k16 < K16TOT; ++k16) {
        if (k16 + (RING - 1) < K16TOT) {
            #pragma unroll
            for (int p = 0; p < NFR; ++p)
                ldg128(bq[(k16 + RING - 1) % RING][p],
                       gw + (size_t)(((k16 + RING - 1) * KSTR + p) * 512));
        }
        if (ALOOK) {
            if (k16 + 1 < K16TOT) {
                #pragma unroll
                for (int mt = 0; mt < MT; ++mt)
                    lds128(a[(k16 + 1) & 1][mt],
                           smA + (uint32_t)((((MTB + mt) * K16TOT + k16 + 1) * 32 + lane) * 16));
            }
        } else {
            #pragma unroll
            for (int mt = 0; mt < MT; ++mt)
                lds128(a[0][mt],
                       smA + (uint32_t)((((MTB + mt) * K16TOT + k16) * 32 + lane) * 16));
        }
        const uint32_t (*ac)[4] = ALOOK ? a[k16 & 1] : a[0];
        #pragma unroll
        for (int p = 0; p < NFR; ++p) {
            const uint32_t* b = bq[k16 % RING][p];
            #pragma unroll
            for (int mt = 0; mt < MT; ++mt) {
                mma16(d + (mt * NT + 2 * p) * 4,     ac[mt], b[0], b[1]);
                mma16(d + (mt * NT + 2 * p + 1) * 4, ac[mt], b[2], b[3]);
            }
        }
    }

    if (MODE == 2) return;

    #pragma unroll
    for (int mt = 0; mt < MT; ++mt) {
        const int r0 = (MTB + mt) * 16 + ri;
        float g0 = 1.f, g1 = 1.f;
        if (MODE == 1) { g0 = gate[r0]; g1 = gate[r0 + 8]; }
        #pragma unroll
        for (int t8 = 0; t8 < NT; ++t8) {
            const int n0 = wn * (NT * 8) + t8 * 8 + 2 * c;
            const float bz0 = __ldg(bias + n0), bz1 = __ldg(bias + n0 + 1);
            const float* dd = d + (mt * NT + t8) * 4;
            float v0 = fmaxf(dd[0] + bz0, 0.f), v1 = fmaxf(dd[1] + bz1, 0.f);
            float v2 = fmaxf(dd[2] + bz0, 0.f), v3 = fmaxf(dd[3] + bz1, 0.f);
            if (MODE == 1) { v0 *= g0; v1 *= g0; v2 *= g1; v3 *= g1; }
            uint32_t h0 = packh(v0, v1), h1 = packh(v2, v3);
            uint32_t dst = smOut
                + (uint32_t)((((MTB + mt) * K16OUT + koff_out + ((wn * NT + t8) >> 1)) * 32
                              + lane) * 16)
                + (uint32_t)((t8 & 1) * 8);
            sts64(dst, h0, h1);
        }
    }
}

// dispatch both wm variants (warp-uniform branch); barrier OUTSIDE
#define STAGE(K16TOT, NT, KSTR, K16OUT, MODE, RING, ALOOK, smA, smOut, koff, gB, bias, gate, dacc) \
    do { if (wm0) stage<4, 0, K16TOT, NT, KSTR, K16OUT, MODE, RING, ALOOK>(                        \
                     smA, smOut, koff, gB, bias, gate, dacc, tid);                                 \
         else     stage<3, 4, K16TOT, NT, KSTR, K16OUT, MODE, RING, ALOOK>(                        \
                     smA, smOut, koff, gB, bias, gate, dacc, tid); } while (0)

// ---------------- main kernel ----------------
__global__ void __launch_bounds__(NTH, 1) moe_f16_kernel(
    const float* __restrict__ x,
    const float* __restrict__ Wg, const float* __restrict__ bg,
    const float* __restrict__ b1, const float* __restrict__ b2,
    const float* __restrict__ b3, const float* __restrict__ b4,
    float* __restrict__ out)
{
    extern __shared__ char smem[];
    const uint32_t smb = smem_u32(smem);
    const uint32_t smX = smb + OFF_SX, smH2 = smb + OFF_H2;
    const uint32_t smH3 = smb + OFF_H3;
    const uint32_t smH64A = smb + OFF_H64A, smH64B = smb + OFF_H64B;
    const uint32_t smGF = smb + OFF_GF;
    float* sWg  = reinterpret_cast<float*>(smem + OFF_H2);
    float* sLog = reinterpret_cast<float*>(smem + OFF_H3);
    float* sG   = reinterpret_cast<float*>(smem + OFF_G);

    const int tid = threadIdx.x;
    const int b0  = blockIdx.x * TOK;

    // ---- x -> A-fragment f16 layout (112 tok, K16=16); OOB tokens -> 0 ----
    for (int i = 0; i < 56; ++i) {
        int u = tid + i * NTH;            // b32 unit over 112 tok x 128 k-pairs
        int tok = u >> 7, k2 = u & 127;
        int k = 2 * k2;
        float2 v = make_float2(0.f, 0.f);
        if (b0 + tok < BTOT)
            v = *reinterpret_cast<const float2*>(x + (size_t)(b0 + tok) * 256 + k);
        uint32_t h = packh(v.x, v.y);
        uint32_t b32i = (uint32_t)(((tok >> 4) * 16 + (k >> 4)) * 128
                      + ((tok & 7) * 4 + ((k >> 1) & 3)) * 4
                      + ((k >> 3) & 1) * 2 + ((tok >> 3) & 1));
        *reinterpret_cast<uint32_t*>(smem + OFF_SX + b32i * 4) = h;
    }
    // Wg -> smem staging (32KB in H2 area)
    {
        const float4* s4 = reinterpret_cast<const float4*>(Wg);
        float4* d4 = reinterpret_cast<float4*>(smem + OFF_H2);
        #pragma unroll
        for (int i = 0; i < 8; ++i) d4[tid + i * NTH] = s4[tid + i * NTH];
    }
    __syncthreads();

    // ---- gating logits (fp32, x from gmem, guarded) ----
    if (tid < 224) {
        int tok = tid >> 1, eg = (tid & 1) * 16;
        float lg[16];
        #pragma unroll
        for (int j = 0; j < 16; ++j) lg[j] = 0.f;
        const bool ok = (b0 + tok < BTOT);
        const float* xr = x + (size_t)(b0 + tok) * 256;
        #pragma unroll 2
        for (int k = 0; k < 256; ++k) {
            float a = ok ? __ldg(xr + k) : 0.f;
            const float* wr = sWg + k * 32 + eg;
            #pragma unroll
            for (int q = 0; q < 4; ++q) {
                float4 w = *reinterpret_cast<const float4*>(wr + 4 * q);
                lg[4*q+0] += a * w.x; lg[4*q+1] += a * w.y;
                lg[4*q+2] += a * w.z; lg[4*q+3] += a * w.w;
            }
        }
        #pragma unroll
        for (int j = 0; j < 16; ++j) sLog[tok * 32 + eg + j] = lg[j] + __ldg(bg + eg + j);
    }
    __syncthreads();
    // softmax; store f32 gates [e][tok] and f16 gate A-fragments (K=32 -> 2 k16)
    if (tid < TOK) {
        float lv[32];
        float m = -1e30f;
        #pragma unroll
        for (int e2 = 0; e2 < 32; ++e2) { lv[e2] = sLog[tid * 32 + e2]; m = fmaxf(m, lv[e2]); }
        float s = 0.f;
        #pragma unroll
        for (int e2 = 0; e2 < 32; ++e2) { lv[e2] = expf(lv[e2] - m); s += lv[e2]; }
        float inv = 1.f / s;
        #pragma unroll
        for (int e2 = 0; e2 < 32; ++e2) lv[e2] *= inv;
        #pragma unroll
        for (int e2 = 0; e2 < 32; ++e2) sG[e2 * TOK + tid] = lv[e2];
        #pragma unroll
        for (int e2 = 0; e2 < 32; e2 += 2) {
            uint32_t h = packh(lv[e2], lv[e2 + 1]);
            uint32_t b32i = (uint32_t)(((tid >> 4) * 2 + (e2 >> 4)) * 128
                          + ((tid & 7) * 4 + ((e2 >> 1) & 3)) * 4
                          + ((e2 >> 3) & 1) * 2 + ((tid >> 3) & 1));
            *reinterpret_cast<uint32_t*>(smem + OFF_GF + b32i * 4) = h;
        }
    }
    __syncthreads();

    // ---- software-pipelined expert loop: S1(e+1) overlaps S5(e) ----
    float dacc[64];
    #pragma unroll
    for (int j = 0; j < 64; ++j) dacc[j] = 0.f;

    const char* gWh = reinterpret_cast<const char*>(g_Wh);
    const bool wm0 = ((tid >> 5) >> 2) == 0;

    // prologue: S1(expert 0)
    STAGE(16, 2, 4, 4, 0, 4, true, smX, smH64A, 0, gWh + BYT_S1,
          b1, nullptr, nullptr);
    __syncthreads();

    for (int e = 0; e < E; ++e) {
        const char* wb = gWh + (size_t)e * EXP_BYTES;
        // S2: K=64, N=256 as two N=128 halves -> H2
        STAGE(4, 4, 16, 16, 0, 3, false, smH64A, smH2, 0, wb + BYT_S2,
              b2 + e * 256, nullptr, nullptr);
        STAGE(4, 4, 16, 16, 0, 3, false, smH64A, smH2, 8, wb + BYT_S2 + 4096,
              b2 + e * 256 + 128, nullptr, nullptr);
        __syncthreads();
        // S3: K=256, N=128 -> H3
        STAGE(16, 4, 8, 8, 0, 3, false, smH2, smH3, 0, wb + BYT_S3,
              b3 + e * 128, nullptr, nullptr);
        __syncthreads();
        // S4: K=128, N=64 -> H64B, relu*gate folded (ring4, A-lookahead)
        STAGE(8, 2, 4, 4, 1, 4, true, smH3, smH64B, 0, wb + BYT_S4,
              b4 + e * 64, sG + e * TOK, nullptr);
        __syncthreads();
        // S5(e): K=64, N=128, accumulate into dacc  — overlapped with S1(e+1)
        STAGE(4, 4, 8, 0, 2, 3, false, smH64B, 0, 0, wb + BYT_S5,
              nullptr, nullptr, dacc);
        if (e + 1 < E) {
            const char* wbn = gWh + (size_t)(e + 1) * EXP_BYTES;
            // S1(e+1): reads smX, writes H64A (last read by S2(e), two barriers ago)
            STAGE(16, 2, 4, 4, 0, 4, true, smX, smH64A, 0, wbn + BYT_S1,
                  b1 + (e + 1) * 64, nullptr, nullptr);
            __syncthreads();
        }
    }

    // ---- bias term: dacc += G[112,32] @ B5[32,128] ----
    STAGE(2, 4, 8, 0, 2, 2, false, smGF, 0, 0, gWh + (size_t)BYT_B5,
          nullptr, nullptr, dacc);

    // ---- write output, guarded ----
    {
        const int lane = tid & 31, wid = tid >> 5;
        const int wn = wid & 3;
        const int ri = lane >> 2, c = lane & 3;
        const int MT = wm0 ? 4 : 3, MTB = wm0 ? 0 : 4;
        for (int mt = 0; mt < MT; ++mt) {
            int r0 = b0 + (MTB + mt) * 16 + ri;
            #pragma unroll
            for (int t8 = 0; t8 < 4; ++t8) {
                int n0 = wn * 32 + t8 * 8 + 2 * c;
                const float* o = dacc + (mt * 4 + t8) * 4;
                float2 v0; v0.x = o[0]; v0.y = o[1];
                float2 v1; v1.x = o[2]; v1.y = o[3];
                if (r0 < BTOT)
                    *reinterpret_cast<float2*>(out + (size_t)r0 * 128 + n0) = v0;
                if (r0 + 8 < BTOT)
                    *reinterpret_cast<float2*>(out + (size_t)(r0 + 8) * 128 + n0) = v1;
            }
        }
    }
}

// ---------------- launcher ----------------
extern "C" void kernel_launch(void* const* d_in, const int* in_sizes, int n_in,
                              void* d_out, int out_size)
{
    (void)in_sizes; (void)n_in; (void)out_size;
    const float* x  = (const float*)d_in[0];
    const float* Wg = (const float*)d_in[1];
    const float* bg = (const float*)d_in[2];
    const float* W1 = (const float*)d_in[3];
    const float* b1 = (const float*)d_in[4];
    const float* W2 = (const float*)d_in[5];
    const float* b2 = (const float*)d_in[6];
    const float* W3 = (const float*)d_in[7];
    const float* b3 = (const float*)d_in[8];
    const float* W4 = (const float*)d_in[9];
    const float* b4 = (const float*)d_in[10];
    const float* W5 = (const float*)d_in[11];
    const float* b5 = (const float*)d_in[12];
    float* out = (float*)d_out;

    repack_all<<<(TOTAL_B32 / 4 + 255) / 256, 256>>>(W1, W2, W3, W4, W5, b5);

    cudaFuncSetAttribute(moe_f16_kernel,
                         cudaFuncAttributeMaxDynamicSharedMemorySize, SMEM_BYTES);
    moe_f16_kernel<<<NCTA, NTH, SMEM_BYTES>>>(x, Wg, bg, b1, b2, b3, b4, out);
}

// round 16
// speedup vs baseline: 1.1451x; 1.0787x over previous
#include <cuda_runtime.h>
#include <cuda_fp16.h>
#include <cstdint>

#define NTH 256

namespace {
constexpr int E    = 32;
constexpr int TOK  = 112;             // 7 m-tiles of 16
constexpr int NCTA = (16384 + TOK - 1) / TOK;   // 147
constexpr int BTOT = 16384;

constexpr int EXP_B32   = 40960;
constexpr int TOTAL_B32 = E * EXP_B32 + 2048;  // + B5 gate-GEMM block
constexpr int TOTAL_F16 = TOTAL_B32 * 2;

// per-expert byte bases inside g_Wh (fragment-linear, full-N blocks)
constexpr int BYT_S1 = 0;        // K=256,N=64
constexpr int BYT_S2 = 32768;    // K=64, N=256
constexpr int BYT_S3 = 65536;    // K=256,N=128
constexpr int BYT_S4 = 131072;   // K=128,N=64
constexpr int BYT_S5 = 147456;   // K=64, N=128
constexpr int EXP_BYTES = 163840;
constexpr int BYT_B5 = E * EXP_BYTES;   // K=32, N=128

// smem byte offsets (7 m-tiles)
constexpr int OFF_SX   = 0;        // x A-frag (K16=16): 57344
constexpr int OFF_H2   = 57344;    // h2 A-frag (K16=16): 57344 (also Wg staging)
constexpr int OFF_H3   = 114688;   // h3 A-frag (K16=8): 28672 (also logits tmp)
constexpr int OFF_H64A = 143360;   // h1 A-frag: 14336
constexpr int OFF_H64B = 157696;   // h4 A-frag: 14336
constexpr int OFF_G    = 172032;   // gates f32 [E][112]: 14336
constexpr int OFF_GF   = 186368;   // gate A-frag f16 (K16=2): 7168
constexpr int SMEM_BYTES = 193536; // 1 CTA/SM

__device__ __align__(16) __half g_Wh[TOTAL_F16];
}

// ---------------- helpers ----------------
__device__ __forceinline__ uint32_t smem_u32(const void* p) {
    uint32_t a;
    asm("{ .reg .u64 t; cvta.to.shared.u64 t, %1; cvt.u32.u64 %0, t; }" : "=r"(a) : "l"(p));
    return a;
}
__device__ __forceinline__ uint32_t packh(float lo, float hi) {
    uint32_t r;
    asm("cvt.rn.f16x2.f32 %0, %1, %2;" : "=r"(r) : "f"(hi), "f"(lo));
    return r;
}
__device__ __forceinline__ void mma16(float* d, const uint32_t* a, uint32_t b0, uint32_t b1) {
    asm volatile("mma.sync.aligned.m16n8k16.row.col.f32.f16.f16.f32 "
        "{%0,%1,%2,%3}, {%4,%5,%6,%7}, {%8,%9}, {%0,%1,%2,%3};"
        : "+f"(d[0]), "+f"(d[1]), "+f"(d[2]), "+f"(d[3])
        : "r"(a[0]), "r"(a[1]), "r"(a[2]), "r"(a[3]), "r"(b0), "r"(b1));
}
__device__ __forceinline__ void lds128(uint32_t* r, uint32_t addr) {
    asm volatile("ld.shared.v4.u32 {%0,%1,%2,%3}, [%4];"
        : "=r"(r[0]), "=r"(r[1]), "=r"(r[2]), "=r"(r[3]) : "r"(addr));
}
__device__ __forceinline__ void sts64(uint32_t addr, uint32_t h0, uint32_t h1) {
    asm volatile("st.shared.v2.u32 [%0], {%1,%2};" :: "r"(addr), "r"(h0), "r"(h1) : "memory");
}
__device__ __forceinline__ void ldg128(uint32_t* r, const char* p) {
    uint4 v = __ldg(reinterpret_cast<const uint4*>(p));
    r[0] = v.x; r[1] = v.y; r[2] = v.z; r[3] = v.w;
}

// ---------------- weight repack (gather form: coalesced 16B writes) ----------------
__global__ void repack_all(const float* __restrict__ W1, const float* __restrict__ W2,
                           const float* __restrict__ W3, const float* __restrict__ W4,
                           const float* __restrict__ W5, const float* __restrict__ b5) {
    int t = blockIdx.x * blockDim.x + threadIdx.x;
    int w0 = t * 4;
    if (w0 >= TOTAL_B32) return;

    const float* W; int K, NSRC, roff; size_t erow = 0;
    if (w0 < E * EXP_B32) {
        int e = w0 / EXP_B32, r = w0 % EXP_B32;
        if      (r <  8192) { W = W1; K = 256; NSRC =  64; roff = r; }
        else if (r < 16384) { W = W2; K =  64; NSRC = 256; roff = r - 8192; }
        else if (r < 32768) { W = W3; K = 256; NSRC = 128; roff = r - 16384; }
        else if (r < 36864) { W = W4; K = 128; NSRC =  64; roff = r - 32768; }
        else                { W = W5; K =  64; NSRC = 128; roff = r - 36864; }
        erow = (size_t)e * K * NSRC;
    } else {
        W = b5; K = 32; NSRC = 128; roff = w0 - E * EXP_B32;
    }

    int block = roff >> 7, inner = roff & 127;
    int nt16 = block % (NSRC >> 4), kt16 = block / (NSRC >> 4);
    int kq = (inner >> 2) & 3, nl = (inner >> 4) & 7;
    int kb = kt16 * 16 + kq * 2, nb = nt16 * 16 + nl;
    const float* src = W + erow;

    uint32_t wv[4];
    #pragma unroll
    for (int i = 0; i < 4; ++i) {
        int k = kb + (i & 1) * 8;
        int n = nb + ((i >> 1) & 1) * 8;
        float lo = src[(size_t)k * NSRC + n];
        float hi = src[(size_t)(k + 1) * NSRC + n];
        wv[i] = packh(lo, hi);
    }
    uint4 o; o.x = wv[0]; o.y = wv[1]; o.z = wv[2]; o.w = wv[3];
    *reinterpret_cast<uint4*>(reinterpret_cast<char*>(g_Wh) + (size_t)w0 * 4) = o;
}

// ---- B-ring preload: fill slots 0..RING-2 before the stage (issue above the barrier) ----
#define PRELOAD(RING, NT, KSTR, K16TOT, gB, bq) do {                                     \
    const int NFR_ = (NT) / 2;                                                           \
    const char* gw_ = (gB) + (size_t)((((tid >> 5) & 3) * NFR_ * 32 + (tid & 31)) * 16); \
    _Pragma("unroll")                                                                    \
    for (int i_ = 0; i_ < (RING) - 1 && i_ < (K16TOT); ++i_)                             \
        _Pragma("unroll")                                                                \
        for (int p_ = 0; p_ < NFR_; ++p_)                                                \
            ldg128((bq) + (i_ * NFR_ + p_) * 4, gw_ + (size_t)((i_ * (KSTR) + p_) * 512));\
} while (0)

// ---------------- fused stage (MT m-tiles starting at MTB, NT n-tiles per warp) ----------------
// MODE 0: relu -> A-frag STS ; MODE 1: relu*gate -> STS ; MODE 2: accumulate into dacc.
// bq: caller-preloaded ring buffer (slots 0..RING-2 filled).
template<int MT, int MTB, int K16TOT, int NT, int KSTR, int K16OUT, int MODE, int RING, bool ALOOK>
__device__ __forceinline__ void stage(
    uint32_t smA, uint32_t smOut, uint32_t koff_out,
    const char* __restrict__ gB,
    const float* __restrict__ bias,
    const float* __restrict__ gate,
    float* __restrict__ dacc,
    int tid, uint32_t* __restrict__ bq)
{
    const int lane = tid & 31;
    const int wn = (tid >> 5) & 3;
    const int c = lane & 3, ri = lane >> 2;
    constexpr int NFR = NT / 2;

    float dtmp[MODE == 2 ? 1 : MT * NT * 4];
    float* d = (MODE == 2) ? dacc : dtmp;
    if (MODE != 2) {
        #pragma unroll
        for (int j = 0; j < MT * NT * 4; ++j) d[j] = 0.f;
    }

    const char* gw = gB + (size_t)((wn * NFR * 32 + lane) * 16);

    uint32_t a[ALOOK ? 2 : 1][MT][4];
    if (ALOOK) {
        #pragma unroll
        for (int mt = 0; mt < MT; ++mt)
            lds128(a[0][mt], smA + (uint32_t)((((MTB + mt) * K16TOT) * 32 + lane) * 16));
    }

    #pragma unroll
    for (int k16 = 0; k16 < K16TOT; ++k16) {
        if (k16 + (RING - 1) < K16TOT) {
            const int slot = (k16 + RING - 1) % RING;
            #pragma unroll
            for (int p = 0; p < NFR; ++p)
                ldg128(bq + (slot * NFR + p) * 4,
                       gw + (size_t)(((k16 + RING - 1) * KSTR + p) * 512));
        }
        if (ALOOK) {
            if (k16 + 1 < K16TOT) {
                #pragma unroll
                for (int mt = 0; mt < MT; ++mt)
                    lds128(a[(k16 + 1) & 1][mt],
                           smA + (uint32_t)((((MTB + mt) * K16TOT + k16 + 1) * 32 + lane) * 16));
            }
        } else {
            #pragma unroll
            for (int mt = 0; mt < MT; ++mt)
                lds128(a[0][mt],
                       smA + (uint32_t)((((MTB + mt) * K16TOT + k16) * 32 + lane) * 16));
        }
        const uint32_t (*ac)[4] = ALOOK ? a[k16 & 1] : a[0];
        #pragma unroll
        for (int p = 0; p < NFR; ++p) {
            const uint32_t* b = bq + ((k16 % RING) * NFR + p) * 4;
            #pragma unroll
            for (int mt = 0; mt < MT; ++mt) {
                mma16(d + (mt * NT + 2 * p) * 4,     ac[mt], b[0], b[1]);
                mma16(d + (mt * NT + 2 * p + 1) * 4, ac[mt], b[2], b[3]);
            }
        }
    }

    if (MODE == 2) return;

    #pragma unroll
    for (int mt = 0; mt < MT; ++mt) {
        const int r0 = (MTB + mt) * 16 + ri;
        float g0 = 1.f, g1 = 1.f;
        if (MODE == 1) { g0 = gate[r0]; g1 = gate[r0 + 8]; }
        #pragma unroll
        for (int t8 = 0; t8 < NT; ++t8) {
            const int n0 = wn * (NT * 8) + t8 * 8 + 2 * c;
            const float bz0 = __ldg(bias + n0), bz1 = __ldg(bias + n0 + 1);
            const float* dd = d + (mt * NT + t8) * 4;
            float v0 = fmaxf(dd[0] + bz0, 0.f), v1 = fmaxf(dd[1] + bz1, 0.f);
            float v2 = fmaxf(dd[2] + bz0, 0.f), v3 = fmaxf(dd[3] + bz1, 0.f);
            if (MODE == 1) { v0 *= g0; v1 *= g0; v2 *= g1; v3 *= g1; }
            uint32_t h0 = packh(v0, v1), h1 = packh(v2, v3);
            uint32_t dst = smOut
                + (uint32_t)((((MTB + mt) * K16OUT + koff_out + ((wn * NT + t8) >> 1)) * 32
                              + lane) * 16)
                + (uint32_t)((t8 & 1) * 8);
            sts64(dst, h0, h1);
        }
    }
}

// dispatch both wm variants (warp-uniform branch); barrier OUTSIDE
#define STAGE(K16TOT, NT, KSTR, K16OUT, MODE, RING, ALOOK, smA, smOut, koff, gB, bias, gate, dacc, bq) \
    do { if (wm0) stage<4, 0, K16TOT, NT, KSTR, K16OUT, MODE, RING, ALOOK>(                            \
                     smA, smOut, koff, gB, bias, gate, dacc, tid, bq);                                 \
         else     stage<3, 4, K16TOT, NT, KSTR, K16OUT, MODE, RING, ALOOK>(                            \
                     smA, smOut, koff, gB, bias, gate, dacc, tid, bq); } while (0)

// ---------------- main kernel ----------------
__global__ void __launch_bounds__(NTH, 1) moe_f16_kernel(
    const float* __restrict__ x,
    const float* __restrict__ Wg, const float* __restrict__ bg,
    const float* __restrict__ b1, const float* __restrict__ b2,
    const float* __restrict__ b3, const float* __restrict__ b4,
    float* __restrict__ out)
{
    extern __shared__ char smem[];
    const uint32_t smb = smem_u32(smem);
    const uint32_t smX = smb + OFF_SX, smH2 = smb + OFF_H2;
    const uint32_t smH3 = smb + OFF_H3;
    const uint32_t smH64A = smb + OFF_H64A, smH64B = smb + OFF_H64B;
    const uint32_t smGF = smb + OFF_GF;
    float* sWg  = reinterpret_cast<float*>(smem + OFF_H2);
    float* sLog = reinterpret_cast<float*>(smem + OFF_H3);
    float* sG   = reinterpret_cast<float*>(smem + OFF_G);

    const int tid = threadIdx.x;
    const int b0  = blockIdx.x * TOK;

    // ---- x -> A-fragment f16 layout (112 tok, K16=16); OOB tokens -> 0 ----
    for (int i = 0; i < 56; ++i) {
        int u = tid + i * NTH;            // b32 unit over 112 tok x 128 k-pairs
        int tok = u >> 7, k2 = u & 127;
        int k = 2 * k2;
        float2 v = make_float2(0.f, 0.f);
        if (b0 + tok < BTOT)
            v = *reinterpret_cast<const float2*>(x + (size_t)(b0 + tok) * 256 + k);
        uint32_t h = packh(v.x, v.y);
        uint32_t b32i = (uint32_t)(((tok >> 4) * 16 + (k >> 4)) * 128
                      + ((tok & 7) * 4 + ((k >> 1) & 3)) * 4
                      + ((k >> 3) & 1) * 2 + ((tok >> 3) & 1));
        *reinterpret_cast<uint32_t*>(smem + OFF_SX + b32i * 4) = h;
    }
    // Wg -> smem staging (32KB in H2 area)
    {
        const float4* s4 = reinterpret_cast<const float4*>(Wg);
        float4* d4 = reinterpret_cast<float4*>(smem + OFF_H2);
        #pragma unroll
        for (int i = 0; i < 8; ++i) d4[tid + i * NTH] = s4[tid + i * NTH];
    }
    __syncthreads();

    // ---- gating logits (fp32, x from gmem, guarded) ----
    if (tid < 224) {
        int tok = tid >> 1, eg = (tid & 1) * 16;
        float lg[16];
        #pragma unroll
        for (int j = 0; j < 16; ++j) lg[j] = 0.f;
        const bool ok = (b0 + tok < BTOT);
        const float* xr = x + (size_t)(b0 + tok) * 256;
        #pragma unroll 2
        for (int k = 0; k < 256; ++k) {
            float a = ok ? __ldg(xr + k) : 0.f;
            const float* wr = sWg + k * 32 + eg;
            #pragma unroll
            for (int q = 0; q < 4; ++q) {
                float4 w = *reinterpret_cast<const float4*>(wr + 4 * q);
                lg[4*q+0] += a * w.x; lg[4*q+1] += a * w.y;
                lg[4*q+2] += a * w.z; lg[4*q+3] += a * w.w;
            }
        }
        #pragma unroll
        for (int j = 0; j < 16; ++j) sLog[tok * 32 + eg + j] = lg[j] + __ldg(bg + eg + j);
    }
    __syncthreads();
    // softmax; store f32 gates [e][tok] and f16 gate A-fragments (K=32 -> 2 k16)
    if (tid < TOK) {
        float lv[32];
        float m = -1e30f;
        #pragma unroll
        for (int e2 = 0; e2 < 32; ++e2) { lv[e2] = sLog[tid * 32 + e2]; m = fmaxf(m, lv[e2]); }
        float s = 0.f;
        #pragma unroll
        for (int e2 = 0; e2 < 32; ++e2) { lv[e2] = expf(lv[e2] - m); s += lv[e2]; }
        float inv = 1.f / s;
        #pragma unroll
        for (int e2 = 0; e2 < 32; ++e2) lv[e2] *= inv;
        #pragma unroll
        for (int e2 = 0; e2 < 32; ++e2) sG[e2 * TOK + tid] = lv[e2];
        #pragma unroll
        for (int e2 = 0; e2 < 32; e2 += 2) {
            uint32_t h = packh(lv[e2], lv[e2 + 1]);
            uint32_t b32i = (uint32_t)(((tid >> 4) * 2 + (e2 >> 4)) * 128
                          + ((tid & 7) * 4 + ((e2 >> 1) & 3)) * 4
                          + ((e2 >> 3) & 1) * 2 + ((tid >> 3) & 1));
            *reinterpret_cast<uint32_t*>(smem + OFF_GF + b32i * 4) = h;
        }
    }

    // ---- pipelined expert loop; B-ring preloads hoisted above every barrier ----
    float dacc[64];
    #pragma unroll
    for (int j = 0; j < 64; ++j) dacc[j] = 0.f;

    const char* gWh = reinterpret_cast<const char*>(g_Wh);
    const bool wm0 = ((tid >> 5) >> 2) == 0;

    uint32_t bqA[32], bqB[32];   // ring buffers (max RING6*NFR1 / RING4*NFR2 = 32 b32)

    // prologue: preload S1(e0) above the softmax barrier
    PRELOAD(6, 2, 4, 16, gWh + BYT_S1, bqB);
    __syncthreads();
    STAGE(16, 2, 4, 4, 0, 6, true, smX, smH64A, 0, gWh + BYT_S1,
          b1, nullptr, nullptr, bqB);

    for (int e = 0; e < E; ++e) {
        const char* wb = gWh + (size_t)e * EXP_BYTES;

        PRELOAD(3, 4, 16, 4, wb + BYT_S2, bqA);
        PRELOAD(3, 4, 16, 4, wb + BYT_S2 + 4096, bqB);
        __syncthreads();                       // H64A ready
        STAGE(4, 4, 16, 16, 0, 3, false, smH64A, smH2, 0, wb + BYT_S2,
              b2 + e * 256, nullptr, nullptr, bqA);
        STAGE(4, 4, 16, 16, 0, 3, false, smH64A, smH2, 8, wb + BYT_S2 + 4096,
              b2 + e * 256 + 128, nullptr, nullptr, bqB);

        PRELOAD(4, 4, 8, 16, wb + BYT_S3, bqA);
        __syncthreads();                       // H2 ready
        STAGE(16, 4, 8, 8, 0, 4, false, smH2, smH3, 0, wb + BYT_S3,
              b3 + e * 128, nullptr, nullptr, bqA);

        PRELOAD(6, 2, 4, 8, wb + BYT_S4, bqA);
        __syncthreads();                       // H3 ready
        STAGE(8, 2, 4, 4, 1, 6, true, smH3, smH64B, 0, wb + BYT_S4,
              b4 + e * 64, sG + e * TOK, nullptr, bqA);

        PRELOAD(3, 4, 8, 4, wb + BYT_S5, bqA);
        if (e + 1 < E) PRELOAD(6, 2, 4, 16, gWh + (size_t)(e + 1) * EXP_BYTES + BYT_S1, bqB);
        else           PRELOAD(2, 4, 8, 2, gWh + (size_t)BYT_B5, bqB);
        __syncthreads();                       // H64B ready
        // S5(e) + S1(e+1) share the interval (disjoint smem: H64B read / smX read+H64A write)
        STAGE(4, 4, 8, 0, 2, 3, false, smH64B, 0, 0, wb + BYT_S5,
              nullptr, nullptr, dacc, bqA);
        if (e + 1 < E) {
            STAGE(16, 2, 4, 4, 0, 6, true, smX, smH64A, 0,
                  gWh + (size_t)(e + 1) * EXP_BYTES + BYT_S1,
                  b1 + (e + 1) * 64, nullptr, nullptr, bqB);
        }
    }

    // ---- bias term: dacc += G[112,32] @ B5[32,128] (bqB preloaded in last iter) ----
    STAGE(2, 4, 8, 0, 2, 2, false, smGF, 0, 0, gWh + (size_t)BYT_B5,
          nullptr, nullptr, dacc, bqB);

    // ---- write output, guarded ----
    {
        const int lane = tid & 31, wid = tid >> 5;
        const int wn = wid & 3;
        const int ri = lane >> 2, c = lane & 3;
        const int MT = wm0 ? 4 : 3, MTB = wm0 ? 0 : 4;
        for (int mt = 0; mt < MT; ++mt) {
            int r0 = b0 + (MTB + mt) * 16 + ri;
            #pragma unroll
            for (int t8 = 0; t8 < 4; ++t8) {
                int n0 = wn * 32 + t8 * 8 + 2 * c;
                const float* o = dacc + (mt * 4 + t8) * 4;
                float2 v0; v0.x = o[0]; v0.y = o[1];
                float2 v1; v1.x = o[2]; v1.y = o[3];
                if (r0 < BTOT)
                    *reinterpret_cast<float2*>(out + (size_t)r0 * 128 + n0) = v0;
                if (r0 + 8 < BTOT)
                    *reinterpret_cast<float2*>(out + (size_t)(r0 + 8) * 128 + n0) = v1;
            }
        }
    }
}

// ---------------- launcher ----------------
extern "C" void kernel_launch(void* const* d_in, const int* in_sizes, int n_in,
                              void* d_out, int out_size)
{
    (void)in_sizes; (void)n_in; (void)out_size;
    const float* x  = (const float*)d_in[0];
    const float* Wg = (const float*)d_in[1];
    const float* bg = (const float*)d_in[2];
    const float* W1 = (const float*)d_in[3];
    const float* b1 = (const float*)d_in[4];
    const float* W2 = (const float*)d_in[5];
    const float* b2 = (const float*)d_in[6];
    const float* W3 = (const float*)d_in[7];
    const float* b3 = (const float*)d_in[8];
    const float* W4 = (const float*)d_in[9];
    const float* b4 = (const float*)d_in[10];
    const float* W5 = (const float*)d_in[11];
    const float* b5 = (const float*)d_in[12];
    float* out = (float*)d_out;

    repack_all<<<(TOTAL_B32 / 4 + 255) / 256, 256>>>(W1, W2, W3, W4, W5, b5);

    cudaFuncSetAttribute(moe_f16_kernel,
                         cudaFuncAttributeMaxDynamicSharedMemorySize, SMEM_BYTES);
    moe_f16_kernel<<<NCTA, NTH, SMEM_BYTES>>>(x, Wg, bg, b1, b2, b3, b4, out);
}